// round 2
// baseline (speedup 1.0000x reference)
#include <cuda_runtime.h>

#define N       8192
#define ALPHA   16.0f

// Scratch (device globals — no allocation allowed in kernel_launch)
__device__ float4 g_pack[N];   // {x, exp(+16x), exp(-16x), (float)label}
__device__ float  g_loss[N];   // per-row loss_i
__device__ int    g_t_is32;    // 1 if targets buffer is int32-packed

// ---------------------------------------------------------------------------
// Kernel 0: detect target dtype layout. JAX without x64 silently demotes the
// requested int64 targets to int32. Scan odd int32 words of the first 16KB
// (valid under both layouts): true-int64 => all are zero hi-words;
// true-int32 => they are labels 1..4095, ~never all zero.
// ---------------------------------------------------------------------------
__global__ void detect_kernel(const int* __restrict__ t32) {
    __shared__ int flag;
    if (threadIdx.x == 0) flag = 0;
    __syncthreads();
    for (int k = threadIdx.x; k < 2048; k += blockDim.x)
        if (t32[2 * k + 1] != 0) atomicOr(&flag, 1);
    __syncthreads();
    if (threadIdx.x == 0) g_t_is32 = flag;
}

// ---------------------------------------------------------------------------
// Kernel 1: precompute exp tables + float labels
// ---------------------------------------------------------------------------
__global__ void prep_kernel(const float* __restrict__ x,
                            const int* __restrict__ t32) {
    int i = blockIdx.x * blockDim.x + threadIdx.x;
    if (i < N) {
        int lbl = g_t_is32 ? t32[i] : t32[2 * i];  // int64 little-endian lo word
        float xi = x[i];
        float4 v;
        v.x = xi;
        v.y = expf(ALPHA * xi);     // A_i
        v.z = expf(-ALPHA * xi);    // B_i
        v.w = (float)lbl;           // labels 0..9 exact in float
        g_pack[i] = v;
    }
}

// ---------------------------------------------------------------------------
// Kernel 2: main O(n^2) pass. 128 blocks x 512 threads. Whole problem in smem.
// Each warp owns 4 contiguous rows; lanes stride over j.
//
// Algebra: exp(alpha*(base - sim)) factors as exp(alpha*base) * exp(-alpha*sim)
// and the exp(alpha*base) factor cancels in pos/(pos+neg), so we use
// w' = exp(-alpha*|xi-xj|) = (xi>=xj) ? B_i*A_j : A_i*B_j   (no per-pair MUFU).
// ---------------------------------------------------------------------------
__global__ void __launch_bounds__(512, 1) main_kernel() {
    extern __shared__ float4 sh[];
    const int tid = threadIdx.x;

    for (int j = tid; j < N; j += 512) sh[j] = g_pack[j];
    __syncthreads();

    const int warp = tid >> 5;
    const int lane = tid & 31;
    const int row0 = (blockIdx.x * 16 + warp) * 4;

    float xi[4], Ai[4], Bi[4], li[4];
#pragma unroll
    for (int r = 0; r < 4; r++) {
        float4 v = sh[row0 + r];        // broadcast (all lanes same addr)
        xi[r] = v.x; Ai[r] = v.y; Bi[r] = v.z; li[r] = v.w;
    }

    // ---- pass 1: threshold = max sim over union (neg | (same & sim<1)) ----
    // self-pair (d=0) is always in the union, so init 0 == max(-inf, 0).
    float th[4] = {0.f, 0.f, 0.f, 0.f};
    for (int j = lane; j < N; j += 32) {
        float4 v = sh[j];
#pragma unroll
        for (int r = 0; r < 4; r++) {
            float d = fabsf(xi[r] - v.x);
            bool  u = (li[r] != v.w) || (d < 1.0f);
            if (u) th[r] = fmaxf(th[r], d);
        }
    }
#pragma unroll
    for (int r = 0; r < 4; r++) {
#pragma unroll
        for (int off = 16; off; off >>= 1)
            th[r] = fmaxf(th[r], __shfl_xor_sync(0xffffffffu, th[r], off));
        // every lane now holds the row threshold
    }

    // ---- pass 2: masked exp-weighted sums ----
    float pa[4] = {0,0,0,0};   // sum over pos_mask           (fallback logit)
    float pb[4] = {0,0,0,0};   // sum over pos_mask & below   (primary logit)
    float ng[4] = {0,0,0,0};   // sum over neg_mask & below
    for (int j = lane; j < N; j += 32) {
        float4 v = sh[j];
#pragma unroll
        for (int r = 0; r < 4; r++) {
            float s = xi[r] - v.x;
            float d = fabsf(s);
            bool  ge = (s >= 0.f);
            float e = (ge ? Bi[r] : Ai[r]) * (ge ? v.y : v.z);
            bool  same  = (li[r] == v.w);
            bool  below = (d < th[r]);     // strict, bit-identical d as pass 1
            if (same & (d < 1.0f)) {
                pa[r] += e;
                if (below) pb[r] += e;
            } else if ((!same) & below) {
                ng[r] += e;
            }
        }
    }
#pragma unroll
    for (int r = 0; r < 4; r++) {
#pragma unroll
        for (int off = 16; off; off >>= 1) {
            pa[r] += __shfl_xor_sync(0xffffffffu, pa[r], off);
            pb[r] += __shfl_xor_sync(0xffffffffu, pb[r], off);
            ng[r] += __shfl_xor_sync(0xffffffffu, ng[r], off);
        }
        if (lane == 0) {
            // has_pos <=> pb > 0 (pos terms are >= exp(-16) > 1e-7, no underflow)
            float p = (pb[r] > 0.f) ? pb[r] : pa[r];   // p >= 1 (self term)
            g_loss[row0 + r] = logf((p + ng[r]) / p);  // = -log(p/(p+n))
        }
    }
}

// ---------------------------------------------------------------------------
// Kernel 3: deterministic finalize — mean loss, precision, last-row stats.
// Reads x / labels from g_pack (dtype-safe).
// ---------------------------------------------------------------------------
__global__ void __launch_bounds__(1024, 1)
finalize_kernel(float* __restrict__ out) {
    __shared__ float s0[1024], s1[1024], s2[1024];
    __shared__ int   c0[1024], c1[1024], c2[1024];
    const int tid = threadIdx.x;

    float ls = 0.f; int pc = 0;
    for (int j = tid; j < N; j += 1024) {
        float l = g_loss[j];
        ls += l;
        pc += (l < 0.6f) ? 1 : 0;
    }

    // last-row (i = N-1) mean pos/neg sim
    const float4 vl = g_pack[N - 1];
    float ps = 0.f, ns = 0.f; int pcnt = 0, ncnt = 0;
    for (int j = tid; j < N; j += 1024) {
        float4 v = g_pack[j];
        float d = fabsf(vl.x - v.x);
        if (v.w == vl.w) {
            if (d < 1.0f) { ps += d; pcnt++; }     // pos_mask = same & sim<1
        } else {
            ns += d; ncnt++;                        // neg_mask = !same
        }
    }

    s0[tid] = ls; s1[tid] = ps; s2[tid] = ns;
    c0[tid] = pc; c1[tid] = pcnt; c2[tid] = ncnt;
    __syncthreads();
    for (int o = 512; o; o >>= 1) {
        if (tid < o) {
            s0[tid] += s0[tid + o]; s1[tid] += s1[tid + o]; s2[tid] += s2[tid + o];
            c0[tid] += c0[tid + o]; c1[tid] += c1[tid + o]; c2[tid] += c2[tid + o];
        }
        __syncthreads();
    }
    if (tid == 0) {
        out[0] = s0[0] / (float)N;                 // loss
        out[1] = (float)c0[0] / (float)N;          // prec
        out[2] = s1[0] / (float)c1[0];             // mean_pos_sim (row n-1)
        out[3] = s2[0] / (float)c2[0];             // mean_neg_sim (row n-1)
    }
}

// ---------------------------------------------------------------------------
extern "C" void kernel_launch(void* const* d_in, const int* in_sizes, int n_in,
                              void* d_out, int out_size) {
    const float* x   = (const float*)d_in[0];
    const int*   t32 = (const int*)d_in[1];
    float*       out = (float*)d_out;

    // 128 KB dynamic smem for main_kernel (idempotent; not a stream op)
    cudaFuncSetAttribute(main_kernel,
                         cudaFuncAttributeMaxDynamicSharedMemorySize, N * 16);

    detect_kernel<<<1, 256>>>(t32);
    prep_kernel<<<N / 256, 256>>>(x, t32);
    main_kernel<<<128, 512, N * 16>>>();
    finalize_kernel<<<1, 1024>>>(out);
}

// round 3
// speedup vs baseline: 1.6076x; 1.6076x over previous
#include <cuda_runtime.h>

#define N       8192
#define ALPHA   16.0f

// Scratch (device globals — no allocation allowed)
__device__ float4   g_pack[N];      // {x, exp(+16x), exp(-16x), (float)label}
__device__ float    g_mn[10], g_mx[10];
__device__ int      g_present;
__device__ float    g_pls[128];     // per-block loss partial sums
__device__ int      g_ppc[128];     // per-block precision counts
__device__ unsigned g_ticket;

// order-preserving float<->uint keys for atomic min/max
__device__ __forceinline__ unsigned fenc(float f) {
    unsigned u = __float_as_uint(f);
    return (u & 0x80000000u) ? ~u : (u | 0x80000000u);
}
__device__ __forceinline__ float fdec(unsigned k) {
    return __uint_as_float((k & 0x80000000u) ? (k & 0x7FFFFFFFu) : ~k);
}

// ---------------------------------------------------------------------------
// Prep (1 block, 1024 thr): dtype-layout detect (JAX silently demotes int64
// targets to int32), exp tables, per-label min/max, last-row stats, ticket reset.
// ---------------------------------------------------------------------------
__global__ void __launch_bounds__(1024, 1)
prep_kernel(const float* __restrict__ x, const int* __restrict__ t32,
            float* __restrict__ out) {
    __shared__ int flag, pres;
    __shared__ unsigned smin[10], smax[10];
    __shared__ float red0[32], red1[32];
    __shared__ int   rc0[32], rc1[32];
    const int tid = threadIdx.x;

    if (tid == 0) { flag = 0; pres = 0; g_ticket = 0u; }
    if (tid < 10) { smin[tid] = 0xFFFFFFFFu; smax[tid] = 0u; }
    __syncthreads();

    // layout detect: odd int32 words of first 16KB are zero iff true int64
    for (int k = tid; k < 2048; k += 1024)
        if (t32[2 * k + 1] != 0) atomicOr(&flag, 1);
    __syncthreads();
    const int is32 = flag;

    for (int i = tid; i < N; i += 1024) {
        int lbl = is32 ? t32[i] : t32[2 * i];   // int64 LE lo word
        float xi = x[i];
        float4 v;
        v.x = xi;
        v.y = expf(ALPHA * xi);
        v.z = expf(-ALPHA * xi);
        v.w = (float)lbl;
        g_pack[i] = v;
        unsigned key = fenc(xi);
        atomicMin(&smin[lbl], key);
        atomicMax(&smax[lbl], key);
        atomicOr(&pres, 1 << lbl);
    }
    __syncthreads();
    if (tid < 10) { g_mn[tid] = fdec(smin[tid]); g_mx[tid] = fdec(smax[tid]); }
    if (tid == 0) g_present = pres;

    // last-row (i = N-1) mean pos/neg sim
    const float xl = x[N - 1];
    const int   ll = is32 ? t32[N - 1] : t32[2 * (N - 1)];
    float ps = 0.f, ns = 0.f; int pc = 0, nc = 0;
    for (int j = tid; j < N; j += 1024) {
        int lj = is32 ? t32[j] : t32[2 * j];
        float d = fabsf(xl - x[j]);
        if (lj == ll) { if (d < 1.0f) { ps += d; pc++; } }
        else          { ns += d; nc++; }
    }
#pragma unroll
    for (int o = 16; o; o >>= 1) {
        ps += __shfl_xor_sync(~0u, ps, o); ns += __shfl_xor_sync(~0u, ns, o);
        pc += __shfl_xor_sync(~0u, pc, o); nc += __shfl_xor_sync(~0u, nc, o);
    }
    const int w = tid >> 5, l = tid & 31;
    if (l == 0) { red0[w] = ps; red1[w] = ns; rc0[w] = pc; rc1[w] = nc; }
    __syncthreads();
    if (w == 0) {
        ps = red0[l]; ns = red1[l]; pc = rc0[l]; nc = rc1[l];
#pragma unroll
        for (int o = 16; o; o >>= 1) {
            ps += __shfl_xor_sync(~0u, ps, o); ns += __shfl_xor_sync(~0u, ns, o);
            pc += __shfl_xor_sync(~0u, pc, o); nc += __shfl_xor_sync(~0u, nc, o);
        }
        if (l == 0) { out[2] = ps / (float)pc; out[3] = ns / (float)nc; }
    }
}

// ---------------------------------------------------------------------------
// Main: single O(n^2) pass (pass-1 replaced by per-label extreme thresholds).
// 128 blocks x 512 threads; whole problem in 128KB smem; warp owns 4 rows.
// w' = exp(-a|xi-xj|) = (xi>=xj ? B_i*A_j : A_i*B_j); exp(a*base) cancels.
// Final reduction fused via last-block ticket.
// ---------------------------------------------------------------------------
__global__ void __launch_bounds__(512, 1) main_kernel(float* __restrict__ out) {
    extern __shared__ float4 sh[];
    __shared__ float mn[10], mx[10];
    __shared__ int presS;
    __shared__ float wls[16];
    __shared__ int   wpc[16];
    __shared__ unsigned lastS;
    const int tid = threadIdx.x;

    if (tid < 10) { mn[tid] = g_mn[tid]; mx[tid] = g_mx[tid]; }
    if (tid == 10) presS = g_present;
    for (int j = tid; j < N; j += 512) sh[j] = g_pack[j];
    __syncthreads();

    const int warp = tid >> 5, lane = tid & 31;
    const int row0 = (blockIdx.x * 16 + warp) * 4;

    float xi[4], Ai[4], Bi[4], li[4], th[4];
#pragma unroll
    for (int r = 0; r < 4; r++) {
        float4 v = sh[row0 + r];           // broadcast
        xi[r] = v.x; Ai[r] = v.y; Bi[r] = v.z; li[r] = v.w; th[r] = 0.f;
    }

    // threshold from per-label extremes: bit-exact same fp op as pass-2 d
    const int pres = presS;
#pragma unroll
    for (int c = 0; c < 10; c++) {
        if ((pres >> c) & 1) {
            const float fc = (float)c;
            const float a = mn[c], b = mx[c];
#pragma unroll
            for (int r = 0; r < 4; r++)
                if (li[r] != fc)
                    th[r] = fmaxf(th[r], fmaxf(fabsf(xi[r] - a), fabsf(xi[r] - b)));
        }
    }
    // slow path: if any row's diff-label max < 1, same-label (sim<1) union
    // members could set the max. Uniform across lanes (regs identical).
    if ((th[0] < 1.f) | (th[1] < 1.f) | (th[2] < 1.f) | (th[3] < 1.f)) {
        for (int j = lane; j < N; j += 32) {
            float4 v = sh[j];
#pragma unroll
            for (int r = 0; r < 4; r++) {
                float d = fabsf(xi[r] - v.x);
                if (li[r] == v.w && d < 1.0f) th[r] = fmaxf(th[r], d);
            }
        }
#pragma unroll
        for (int r = 0; r < 4; r++)
#pragma unroll
            for (int o = 16; o; o >>= 1)
                th[r] = fmaxf(th[r], __shfl_xor_sync(~0u, th[r], o));
    }

    // single O(n^2) pass: masked exp-weighted sums
    float pb[4] = {0, 0, 0, 0};   // pos & below  (self always qualifies if th>0)
    float ng[4] = {0, 0, 0, 0};   // neg & below
#pragma unroll 2
    for (int j = lane; j < N; j += 32) {
        float4 v = sh[j];
#pragma unroll
        for (int r = 0; r < 4; r++) {
            float s = xi[r] - v.x;
            float d = fabsf(s);
            bool  ge = (s >= 0.f);
            float e = (ge ? Bi[r] : Ai[r]) * (ge ? v.y : v.z);
            bool  same  = (li[r] == v.w);
            bool  below = (d < th[r]);     // strict; identical fp as th source
            if (same && (d < 1.0f) && below) pb[r] += e;
            if (!same && below)              ng[r] += e;
        }
    }

    float ls = 0.f; int pc = 0;
#pragma unroll
    for (int r = 0; r < 4; r++) {
#pragma unroll
        for (int o = 16; o; o >>= 1) {
            pb[r] += __shfl_xor_sync(~0u, pb[r], o);
            ng[r] += __shfl_xor_sync(~0u, ng[r], o);
        }
        if (lane == 0) {
            // th>0 => self in pos_neig => pb>=~1. th==0 => below empty =>
            // pos_sel = pos_mask, neg_sel empty => loss = -log(p/p) = 0.
            float loss = (th[r] > 0.f) ? logf((pb[r] + ng[r]) / pb[r]) : 0.f;
            ls += loss;
            pc += (loss < 0.6f) ? 1 : 0;
        }
    }
    if (lane == 0) { wls[warp] = ls; wpc[warp] = pc; }
    __syncthreads();
    if (tid < 32) {
        float v = (tid < 16) ? wls[tid] : 0.f;
        int   c = (tid < 16) ? wpc[tid] : 0;
#pragma unroll
        for (int o = 16; o; o >>= 1) {
            v += __shfl_xor_sync(~0u, v, o);
            c += __shfl_xor_sync(~0u, c, o);
        }
        if (tid == 0) {
            g_pls[blockIdx.x] = v;
            g_ppc[blockIdx.x] = c;
            __threadfence();
            lastS = atomicAdd(&g_ticket, 1u);
        }
    }
    __syncthreads();
    if (lastS == 127u) {               // last block finalizes (deterministic order)
        __threadfence();
        if (tid < 128) {
            float v = g_pls[tid]; int c = g_ppc[tid];
#pragma unroll
            for (int o = 16; o; o >>= 1) {
                v += __shfl_xor_sync(~0u, v, o);
                c += __shfl_xor_sync(~0u, c, o);
            }
            if ((tid & 31) == 0) { wls[tid >> 5] = v; wpc[tid >> 5] = c; }
        }
        __syncthreads();
        if (tid == 0) {
            float v = wls[0] + wls[1] + wls[2] + wls[3];
            int   c = wpc[0] + wpc[1] + wpc[2] + wpc[3];
            out[0] = v / (float)N;
            out[1] = (float)c / (float)N;
        }
    }
}

// ---------------------------------------------------------------------------
extern "C" void kernel_launch(void* const* d_in, const int* in_sizes, int n_in,
                              void* d_out, int out_size) {
    const float* x   = (const float*)d_in[0];
    const int*   t32 = (const int*)d_in[1];
    float*       out = (float*)d_out;

    cudaFuncSetAttribute(main_kernel,
                         cudaFuncAttributeMaxDynamicSharedMemorySize, N * 16);

    prep_kernel<<<1, 1024>>>(x, t32, out);
    main_kernel<<<128, 512, N * 16>>>(out);
}

// round 4
// speedup vs baseline: 1.8967x; 1.1798x over previous
#include <cuda_runtime.h>

#define N            8192
#define ALPHA        16.0f
#define MAIN_BLOCKS  296
#define MAIN_THREADS 448              // 14 warps
#define MAIN_WARPS   14
#define NTILES       (N / 2)          // 4096 two-row tiles
#define FIXP         4194304.0f       // 2^22 fixed-point scale

// ---- device globals (no allocation allowed) -------------------------------
__device__ float         g_x[N];
__device__ float2        g_AB[N];            // {exp(+16x), exp(-16x)}
__device__ unsigned char g_lab[N];
__device__ float         g_loss[N];
__device__ unsigned g_smin[10] = {0xFFFFFFFFu,0xFFFFFFFFu,0xFFFFFFFFu,0xFFFFFFFFu,
                                  0xFFFFFFFFu,0xFFFFFFFFu,0xFFFFFFFFu,0xFFFFFFFFu,
                                  0xFFFFFFFFu,0xFFFFFFFFu};
__device__ unsigned g_smax[10] = {0,0,0,0,0,0,0,0,0,0};
__device__ unsigned long long g_ps = 0ull, g_ns = 0ull;   // fixed-point sums
__device__ unsigned g_pc = 0u, g_nc = 0u;
__device__ unsigned g_ticket = 0u;

// order-preserving float<->uint keys
__device__ __forceinline__ unsigned fenc(float f) {
    unsigned u = __float_as_uint(f);
    return (u & 0x80000000u) ? ~u : (u | 0x80000000u);
}
__device__ __forceinline__ float fdec(unsigned k) {
    return __uint_as_float((k & 0x80000000u) ? (k & 0x7FFFFFFFu) : ~k);
}

// ---------------------------------------------------------------------------
// Prep: 32 blocks x 256. Layout detect (JAX demotes int64->int32; odd words of
// first 16KB are zero iff true int64), exp tables, per-label min/max (global
// encoded atomics), last-row stats (deterministic fixed-point atomics).
// ---------------------------------------------------------------------------
__global__ void __launch_bounds__(256) prep_kernel(const float* __restrict__ x,
                                                   const int* __restrict__ t32) {
    __shared__ int flag;
    __shared__ unsigned long long rps[8], rns[8];
    __shared__ int rpc[8], rnc[8];
    const int tid = threadIdx.x;
    if (tid == 0) flag = 0;
    __syncthreads();
    for (int k = tid; k < 2048; k += 256)
        if (t32[2 * k + 1] != 0) atomicOr(&flag, 1);
    __syncthreads();
    const int is32 = flag;

    const int i = blockIdx.x * 256 + tid;          // grid covers exactly N
    const float xi = x[i];
    const int lbl = is32 ? t32[i] : t32[2 * i];    // int64 LE lo word
    g_x[i] = xi;
    g_AB[i] = make_float2(expf(ALPHA * xi), expf(-ALPHA * xi));
    g_lab[i] = (unsigned char)lbl;
    unsigned key = fenc(xi);
    atomicMin(&g_smin[lbl], key);
    atomicMax(&g_smax[lbl], key);

    // last-row (i = N-1) pos/neg sim partials, fixed point for determinism
    const float xl = x[N - 1];
    const int   ll = is32 ? t32[N - 1] : t32[2 * (N - 1)];
    float d = fabsf(xl - xi);
    unsigned long long pq = 0ull, nq = 0ull; int pc = 0, nc = 0;
    if (lbl == ll) { if (d < 1.0f) { pq = (unsigned long long)(d * FIXP + 0.5f); pc = 1; } }
    else           { nq = (unsigned long long)(d * FIXP + 0.5f); nc = 1; }
#pragma unroll
    for (int o = 16; o; o >>= 1) {
        pq += __shfl_xor_sync(~0u, pq, o); nq += __shfl_xor_sync(~0u, nq, o);
        pc += __shfl_xor_sync(~0u, pc, o); nc += __shfl_xor_sync(~0u, nc, o);
    }
    const int w = tid >> 5, l = tid & 31;
    if (l == 0) { rps[w] = pq; rns[w] = nq; rpc[w] = pc; rnc[w] = nc; }
    __syncthreads();
    if (tid == 0) {
        unsigned long long sp = 0ull, sn = 0ull; int cp = 0, cn = 0;
        for (int k = 0; k < 8; k++) { sp += rps[k]; sn += rns[k]; cp += rpc[k]; cn += rnc[k]; }
        atomicAdd(&g_ps, sp); atomicAdd(&g_ns, sn);
        atomicAdd(&g_pc, (unsigned)cp); atomicAdd(&g_nc, (unsigned)cn);
    }
}

// ---------------------------------------------------------------------------
// Main: 296 blocks x 448 thr, 2 blocks/SM (104KB dyn smem). Warp g < 4096 owns
// rows {2g, 2g+1}. Threshold from per-label extremes (O(10), bit-exact fp ops);
// single O(n^2) pass with e = min(Bi*Aj, Ai*Bj). Ticket-last block finalizes
// loss/prec + last-row stats and resets globals for graph replay.
// ---------------------------------------------------------------------------
__global__ void __launch_bounds__(MAIN_THREADS, 2) main_kernel(float* __restrict__ out) {
    extern __shared__ unsigned char dyn[];
    float2*        sh_AB  = (float2*)dyn;                 // 64KB
    float*         sh_x   = (float*)(dyn + 65536);        // 32KB
    unsigned char* sh_lab = dyn + 98304;                  //  8KB
    __shared__ float s_mn[10], s_mx[10];
    __shared__ int   s_prs[10];
    __shared__ float rls[MAIN_WARPS];
    __shared__ int   rpc[MAIN_WARPS];
    __shared__ unsigned lastS;
    const int tid = threadIdx.x;

    for (int i = tid; i < N; i += MAIN_THREADS) {
        sh_AB[i] = g_AB[i];
        sh_x[i]  = g_x[i];
        sh_lab[i] = g_lab[i];
    }
    if (tid < 10) {
        unsigned mnk = g_smin[tid], mxk = g_smax[tid];
        s_prs[tid] = (mnk != 0xFFFFFFFFu);
        s_mn[tid] = fdec(mnk); s_mx[tid] = fdec(mxk);
    }
    __syncthreads();

    const int warp = tid >> 5, lane = tid & 31;
    const int tile = blockIdx.x * MAIN_WARPS + warp;
    float ls = 0.f; int lpc = 0;

    if (tile < NTILES) {
        const int r0 = 2 * tile, r1 = r0 + 1;
        const float x0 = sh_x[r0], x1 = sh_x[r1];
        const float2 ab0 = sh_AB[r0], ab1 = sh_AB[r1];
        const int l0 = sh_lab[r0], l1 = sh_lab[r1];

        // thresholds from per-label extremes (exact same fp op as inner d)
        float th0 = 0.f, th1 = 0.f;
#pragma unroll
        for (int c = 0; c < 10; c++) {
            if (s_prs[c]) {
                float a = s_mn[c], b = s_mx[c];
                float m = fmaxf(fabsf(x0 - a), fabsf(x0 - b));
                float m2 = fmaxf(fabsf(x1 - a), fabsf(x1 - b));
                if (l0 != c) th0 = fmaxf(th0, m);
                if (l1 != c) th1 = fmaxf(th1, m2);
            }
        }
        // slow path: same-label (d<1) members can set the max if neg max < 1
        if (th0 < 1.f || th1 < 1.f) {
            for (int j = lane; j < N; j += 32) {
                float xj = sh_x[j]; int lj = sh_lab[j];
                float d0 = fabsf(x0 - xj), d1 = fabsf(x1 - xj);
                if (lj == l0 && d0 < 1.f) th0 = fmaxf(th0, d0);
                if (lj == l1 && d1 < 1.f) th1 = fmaxf(th1, d1);
            }
#pragma unroll
            for (int o = 16; o; o >>= 1) {
                th0 = fmaxf(th0, __shfl_xor_sync(~0u, th0, o));
                th1 = fmaxf(th1, __shfl_xor_sync(~0u, th1, o));
            }
        }
        const float pm0 = fminf(1.0f, th0);   // pos: same & d<1 & d<th == d<pm
        const float pm1 = fminf(1.0f, th1);

        float pb0 = 0.f, ng0 = 0.f, pb1 = 0.f, ng1 = 0.f;
#pragma unroll 4
        for (int j = lane; j < N; j += 32) {
            const float  xj = sh_x[j];
            const float2 ab = sh_AB[j];
            const int    lj = sh_lab[j];
            // e = exp(-a|xi-xj|) = min(Bi*Aj, Ai*Bj); overflow side -> inf, min ok
            float d0 = fabsf(x0 - xj);
            float e0 = fminf(ab0.y * ab.x, ab0.x * ab.y);
            bool  s0 = (lj == l0);
            if ( s0 & (d0 < pm0)) pb0 += e0;
            if (!s0 & (d0 < th0)) ng0 += e0;
            float d1 = fabsf(x1 - xj);
            float e1 = fminf(ab1.y * ab.x, ab1.x * ab.y);
            bool  s1 = (lj == l1);
            if ( s1 & (d1 < pm1)) pb1 += e1;
            if (!s1 & (d1 < th1)) ng1 += e1;
        }
#pragma unroll
        for (int o = 16; o; o >>= 1) {
            pb0 += __shfl_xor_sync(~0u, pb0, o); ng0 += __shfl_xor_sync(~0u, ng0, o);
            pb1 += __shfl_xor_sync(~0u, pb1, o); ng1 += __shfl_xor_sync(~0u, ng1, o);
        }
        if (lane == 0) {
            // th>0 => self (d=0) in pos_neig => pb ~>= 1. th==0 => loss 0.
            float L0 = (th0 > 0.f) ? logf((pb0 + ng0) / pb0) : 0.f;
            float L1 = (th1 > 0.f) ? logf((pb1 + ng1) / pb1) : 0.f;
            g_loss[r0] = L0; g_loss[r1] = L1;
            ls = L0 + L1;
            lpc = (L0 < 0.6f) + (L1 < 0.6f);
        }
    }

    __syncthreads();
    if (tid == 0) {
        __threadfence();
        lastS = atomicAdd(&g_ticket, 1u);
    }
    __syncthreads();

    if (lastS == MAIN_BLOCKS - 1) {     // last block finalizes, fixed order
        __threadfence();
        float s = 0.f; int c = 0;
        for (int i = tid; i < N; i += MAIN_THREADS) {
            float l = g_loss[i];
            s += l; c += (l < 0.6f) ? 1 : 0;
        }
#pragma unroll
        for (int o = 16; o; o >>= 1) {
            s += __shfl_xor_sync(~0u, s, o);
            c += __shfl_xor_sync(~0u, c, o);
        }
        if (lane == 0) { rls[warp] = s; rpc[warp] = c; }
        __syncthreads();
        if (tid == 0) {
            float fs = 0.f; int fc = 0;
            for (int k = 0; k < MAIN_WARPS; k++) { fs += rls[k]; fc += rpc[k]; }
            out[0] = fs / (float)N;
            out[1] = (float)fc / (float)N;
            out[2] = ((float)g_ps / FIXP) / (float)g_pc;
            out[3] = ((float)g_ns / FIXP) / (float)g_nc;
            // reset globals for next graph replay
            for (int k = 0; k < 10; k++) { g_smin[k] = 0xFFFFFFFFu; g_smax[k] = 0u; }
            g_ps = 0ull; g_ns = 0ull; g_pc = 0u; g_nc = 0u;
            g_ticket = 0u;
        }
    }
}

// ---------------------------------------------------------------------------
extern "C" void kernel_launch(void* const* d_in, const int* in_sizes, int n_in,
                              void* d_out, int out_size) {
    const float* x   = (const float*)d_in[0];
    const int*   t32 = (const int*)d_in[1];
    float*       out = (float*)d_out;

    cudaFuncSetAttribute(main_kernel,
                         cudaFuncAttributeMaxDynamicSharedMemorySize, 106496);

    prep_kernel<<<N / 256, 256>>>(x, t32);
    main_kernel<<<MAIN_BLOCKS, MAIN_THREADS, 106496>>>(out);
}